// round 15
// baseline (speedup 1.0000x reference)
#include <cuda_runtime.h>
#include <cuda_fp16.h>

// BilateralSliceApply on GB300 — R15: R12 core + paired-z SMEM layout.
// Pair q (q = ifz+1, 0..8) = [cell(max(q-1,0)) | cell(min(q,7))], 48 B contiguous.
// Inner loop: NO z clamps, 2 tap addresses, 6x LDS.128, 24 HFMA2 — arithmetic
// identical to R12 (boundary duplication == clamped double-tap).
// grid:  (4, 12, 8, 16, 16) f32
// guide: (4, 1024, 1024) f32
// image: (4, 3, 1024, 1024) f32
// out:   (4, 3, 1024, 1024) f32

#define GD 8
#define GH 16
#define GW 16
#define NC 12
#define W_IMG 1024
#define H_IMG 1024
#define GRID_PER_B (NC * GD * GH * GW)   // 24576
#define ROWS_PER_BLOCK 4

// Paired-z fp16 SMEM layout, uint (half2) units:
//   pair entry (q,x): 12 uints = 48 B  ->  lower cell c0..c11 (6 uints), upper cell (6 uints)
//   x-stride   = 12 uints (48 B)
//   pair-slice = 16 cells * 48 B = 768 B + 16 B pad = 784 B -> QS = 196 uints
//   784 mod 128 = 16  =>  distinct 16-B bank group per q (mod 8) within x-uniform phases.
#define XUP 12
#define QS 196
#define ROW_U (9 * QS)   // 1764 uints per row buffer (7056 B); 4 rows = 27.6 KB

__device__ __forceinline__ __half2 u2h(unsigned int u) {
    __half2 h;
    *reinterpret_cast<unsigned int*>(&h) = u;
    return h;
}

__global__ void __launch_bounds__(256, 4) bsa_kernel(
    const float* __restrict__ grid,
    const float* __restrict__ guide,
    const float* __restrict__ image,
    float* __restrict__ out)
{
    __shared__ __align__(16) unsigned int sg2[ROWS_PER_BLOCK][ROW_U];

    const int b   = blockIdx.y;
    const int tid = threadIdx.x;

    const float* gb = grid  + b * GRID_PER_B;
    const float* gu = guide + b * (H_IMG * W_IMG);
    const float* im = image + b * 3 * (H_IMG * W_IMG);
    float*       ob = out   + b * 3 * (H_IMG * W_IMG);

    const int row0 = blockIdx.x * ROWS_PER_BLOCK;

    // ---- x-interpolation state: invariant for the whole CTA, 4 columns ----
    int   cox0[4], cox1[4];
    float wxa[4], wxb[4];
    #pragma unroll
    for (int j = 0; j < 4; ++j) {
        const int px = tid + (j << 8);
        const float gx  = ((float)px + 0.5f) * (16.0f / 1024.0f);
        const float fxm = floorf(gx - 0.5f);
        const float tx  = gx - 0.5f - fxm;
        const int   ifx = (int)fxm;
        const int   ix0 = min(max(ifx, 0), GW - 1);
        const int   ix1 = min(max(ifx + 1, 0), GW - 1);
        cox0[j] = ix0 * XUP;
        cox1[j] = ix1 * XUP;
        wxa[j]  = 1.0f - tx;
        wxb[j]  = tx;
    }

    // ---- stage all 4 rows: y-prefold fp32 -> fp16, paired-z writes; one barrier ----
    #pragma unroll
    for (int r = 0; r < ROWS_PER_BLOCK; ++r) {
        const int y = row0 + r;
        const float gyv = ((float)y + 0.5f) * (16.0f / 1024.0f);
        const float fym = floorf(gyv - 0.5f);
        const float ty  = gyv - 0.5f - fym;
        const int   ify = (int)fym;
        const int   iy0 = min(max(ify, 0), GH - 1);
        const int   iy1 = min(max(ify + 1, 0), GH - 1);
        const float wy0 = 1.0f - ty, wy1 = ty;

        // 768 channel-pairs per row: p = (cp*8 + z)*16 + x  (coalesced LDG over x)
        #pragma unroll
        for (int t = 0; t < 3; ++t) {
            const int p  = tid + t * 256;
            const int cp = p >> 7;
            const int z  = (p >> 4) & 7;
            const int x  = p & 15;
            const float* g0 = gb + (2 * cp)     * (GD * GH * GW) + z * (GH * GW) + x;
            const float* g1 = gb + (2 * cp + 1) * (GD * GH * GW) + z * (GH * GW) + x;
            const float f0 = wy0 * g0[iy0 * GW] + wy1 * g0[iy1 * GW];
            const float f1 = wy0 * g1[iy0 * GW] + wy1 * g1[iy1 * GW];
            __half2 h = __floats2half2_rn(f0, f1);
            const unsigned int hv = *reinterpret_cast<unsigned int*>(&h);

            const int cell = x * XUP + cp;
            // cell z is the UPPER of pair q=z and the LOWER of pair q=z+1
            sg2[r][z * QS + cell + 6]       = hv;
            sg2[r][(z + 1) * QS + cell]     = hv;
            if (z == 0) sg2[r][cell]            = hv;   // lower of pair 0
            if (z == 7) sg2[r][8 * QS + cell + 6] = hv; // upper of pair 8
        }
    }
    __syncthreads();   // the only barrier

    // ---- process rows; lane tid owns pixels tid + 256*j ----
    #pragma unroll 1
    for (int r = 0; r < ROWS_PER_BLOCK; ++r) {
        const int y = row0 + r;
        const int rowoff = y * W_IMG;
        const unsigned int* rowbuf = sg2[r];

        // batch the 4 guide loads (head of the longest dependency chain)
        float gv[4];
        #pragma unroll
        for (int j = 0; j < 4; ++j)
            gv[j] = gu[rowoff + tid + (j << 8)];

        #pragma unroll
        for (int j = 0; j < 4; ++j) {
            const int px = tid + (j << 8);

            const float R  = im[0 * 1048576 + rowoff + px];
            const float G  = im[1 * 1048576 + rowoff + px];
            const float Bc = im[2 * 1048576 + rowoff + px];

            // z interpolation — NO clamps: q = ifz+1 in [0,8] by construction
            const float gz  = gv[j] * 8.0f;
            const float fzm = floorf(gz - 0.5f);
            const float tz  = gz - 0.5f - fzm;
            const int   q   = (int)fzm + 1;
            const float wz0 = 1.0f - tz, wz1 = tz;

            const int oA = q * QS + cox0[j];   // x0 pair
            const int oB = q * QS + cox1[j];   // x1 pair

            // ---- 6 LDS.128 back-to-back ----
            const uint4 a4 = *reinterpret_cast<const uint4*>(rowbuf + oA);
            const uint4 b4 = *reinterpret_cast<const uint4*>(rowbuf + oA + 4);
            const uint4 c4 = *reinterpret_cast<const uint4*>(rowbuf + oA + 8);
            const uint4 d4 = *reinterpret_cast<const uint4*>(rowbuf + oB);
            const uint4 e4 = *reinterpret_cast<const uint4*>(rowbuf + oB + 4);
            const uint4 f4 = *reinterpret_cast<const uint4*>(rowbuf + oB + 8);

            const __half2 wLoA = __float2half2_rn(wz0 * wxa[j]);
            const __half2 wHiA = __float2half2_rn(wz1 * wxa[j]);
            const __half2 wLoB = __float2half2_rn(wz0 * wxb[j]);
            const __half2 wHiB = __float2half2_rn(wz1 * wxb[j]);

            // ---- 24 HFMA2 ----
            __half2 a0, a1, a2, a3, a4h, a5;
            // x-tap A, lower cell (z0)
            a0  = __hmul2(u2h(a4.x), wLoA);
            a1  = __hmul2(u2h(a4.y), wLoA);
            a2  = __hmul2(u2h(a4.z), wLoA);
            a3  = __hmul2(u2h(a4.w), wLoA);
            a4h = __hmul2(u2h(b4.x), wLoA);
            a5  = __hmul2(u2h(b4.y), wLoA);
            // x-tap A, upper cell (z1)
            a0  = __hfma2(u2h(b4.z), wHiA, a0);
            a1  = __hfma2(u2h(b4.w), wHiA, a1);
            a2  = __hfma2(u2h(c4.x), wHiA, a2);
            a3  = __hfma2(u2h(c4.y), wHiA, a3);
            a4h = __hfma2(u2h(c4.z), wHiA, a4h);
            a5  = __hfma2(u2h(c4.w), wHiA, a5);
            // x-tap B, lower cell (z0)
            a0  = __hfma2(u2h(d4.x), wLoB, a0);
            a1  = __hfma2(u2h(d4.y), wLoB, a1);
            a2  = __hfma2(u2h(d4.z), wLoB, a2);
            a3  = __hfma2(u2h(d4.w), wLoB, a3);
            a4h = __hfma2(u2h(e4.x), wLoB, a4h);
            a5  = __hfma2(u2h(e4.y), wLoB, a5);
            // x-tap B, upper cell (z1)
            a0  = __hfma2(u2h(e4.z), wHiB, a0);
            a1  = __hfma2(u2h(e4.w), wHiB, a1);
            a2  = __hfma2(u2h(f4.x), wHiB, a2);
            a3  = __hfma2(u2h(f4.y), wHiB, a3);
            a4h = __hfma2(u2h(f4.z), wHiB, a4h);
            a5  = __hfma2(u2h(f4.w), wHiB, a5);

            const float2 p0 = __half22float2(a0);
            const float2 p1 = __half22float2(a1);
            const float2 p2 = __half22float2(a2);
            const float2 p3 = __half22float2(a3);
            const float2 p4 = __half22float2(a4h);
            const float2 p5 = __half22float2(a5);

            ob[0 * 1048576 + rowoff + px] =
                fmaf(p0.x, R, fmaf(p0.y, G, fmaf(p1.x, Bc, p1.y)));
            ob[1 * 1048576 + rowoff + px] =
                fmaf(p2.x, R, fmaf(p2.y, G, fmaf(p3.x, Bc, p3.y)));
            ob[2 * 1048576 + rowoff + px] =
                fmaf(p4.x, R, fmaf(p4.y, G, fmaf(p5.x, Bc, p5.y)));
        }
    }
}

extern "C" void kernel_launch(void* const* d_in, const int* in_sizes, int n_in,
                              void* d_out, int out_size)
{
    const float* grid  = nullptr;
    const float* guide = nullptr;
    const float* image = nullptr;
    for (int i = 0; i < n_in; ++i) {
        if (in_sizes[i] == 4 * GRID_PER_B)             grid  = (const float*)d_in[i];
        else if (in_sizes[i] == 4 * H_IMG * W_IMG)     guide = (const float*)d_in[i];
        else if (in_sizes[i] == 4 * 3 * H_IMG * W_IMG) image = (const float*)d_in[i];
    }
    float* out = (float*)d_out;

    dim3 gr(H_IMG / ROWS_PER_BLOCK, 4);   // 256 x 4 = 1024 blocks, 4 rows each
    bsa_kernel<<<gr, 256>>>(grid, guide, image, out);
}

// round 16
// speedup vs baseline: 1.2195x; 1.2195x over previous
#include <cuda_runtime.h>
#include <cuda_fp16.h>

// BilateralSliceApply on GB300 — R16: R12 tap core (fp16 SMEM + HFMA2,
// strided px, conflict-free phases) with ALL 16 DRAM loads per row batched
// back-to-back (4 guide + 12 image) to maximize DRAM MLP.
// grid:  (4, 12, 8, 16, 16) f32
// guide: (4, 1024, 1024) f32
// image: (4, 3, 1024, 1024) f32
// out:   (4, 3, 1024, 1024) f32

#define GD 8
#define GH 16
#define GW 16
#define NC 12
#define W_IMG 1024
#define H_IMG 1024
#define GRID_PER_B (NC * GD * GH * GW)   // 24576
#define ROWS_PER_BLOCK 4

// fp16 SMEM layout in half2 (uint) units:
//   cell (z,x): 6 half2 used, padded to 8 (32 B)     -> XU = 8
//   z-slice: 16 cells * 32 B = 512 B + 16 B pad = 528 B (132 uints) -> ZU = 132
//   528 mod 128 = 16  =>  distinct 16-B bank group per z within an x-uniform phase.
#define XU 8
#define ZU 132
#define ROW_U (GD * ZU)   // 1056 uints per row buffer (4224 B)

__device__ __forceinline__ __half2 u2h(unsigned int u) {
    __half2 h;
    *reinterpret_cast<unsigned int*>(&h) = u;
    return h;
}

__global__ void __launch_bounds__(256, 4) bsa_kernel(
    const float* __restrict__ grid,
    const float* __restrict__ guide,
    const float* __restrict__ image,
    float* __restrict__ out)
{
    __shared__ __align__(16) unsigned int sg2[ROWS_PER_BLOCK][ROW_U];

    const int b   = blockIdx.y;
    const int tid = threadIdx.x;

    const float* gb = grid  + b * GRID_PER_B;
    const float* gu = guide + b * (H_IMG * W_IMG);
    const float* im = image + b * 3 * (H_IMG * W_IMG);
    float*       ob = out   + b * 3 * (H_IMG * W_IMG);

    const int row0 = blockIdx.x * ROWS_PER_BLOCK;

    // ---- x-interpolation state: invariant for the whole CTA, 4 columns ----
    int   cox0[4], cox1[4];
    float wxa[4], wxb[4];
    #pragma unroll
    for (int j = 0; j < 4; ++j) {
        const int px = tid + (j << 8);
        const float gx  = ((float)px + 0.5f) * (16.0f / 1024.0f);
        const float fxm = floorf(gx - 0.5f);
        const float tx  = gx - 0.5f - fxm;
        const int   ifx = (int)fxm;
        const int   ix0 = min(max(ifx, 0), GW - 1);
        const int   ix1 = min(max(ifx + 1, 0), GW - 1);
        cox0[j] = ix0 * XU;
        cox1[j] = ix1 * XU;
        wxa[j]  = 1.0f - tx;
        wxb[j]  = tx;
    }

    // ---- stage all 4 rows: y-prefold in fp32, store fp16 pairs; one barrier ----
    #pragma unroll
    for (int r = 0; r < ROWS_PER_BLOCK; ++r) {
        const int y = row0 + r;
        const float gyv = ((float)y + 0.5f) * (16.0f / 1024.0f);
        const float fym = floorf(gyv - 0.5f);
        const float ty  = gyv - 0.5f - fym;
        const int   ify = (int)fym;
        const int   iy0 = min(max(ify, 0), GH - 1);
        const int   iy1 = min(max(ify + 1, 0), GH - 1);
        const float wy0 = 1.0f - ty, wy1 = ty;

        // 768 channel-pairs per row: p = (cp*8 + z)*16 + x  (coalesced LDG over x)
        #pragma unroll
        for (int t = 0; t < 3; ++t) {
            const int p  = tid + t * 256;
            const int cp = p >> 7;
            const int z  = (p >> 4) & 7;
            const int x  = p & 15;
            const float* g0 = gb + (2 * cp)     * (GD * GH * GW) + z * (GH * GW) + x;
            const float* g1 = gb + (2 * cp + 1) * (GD * GH * GW) + z * (GH * GW) + x;
            const float f0 = wy0 * g0[iy0 * GW] + wy1 * g0[iy1 * GW];
            const float f1 = wy0 * g1[iy0 * GW] + wy1 * g1[iy1 * GW];
            __half2 h = __floats2half2_rn(f0, f1);
            sg2[r][z * ZU + x * XU + cp] = *reinterpret_cast<unsigned int*>(&h);
        }
    }
    __syncthreads();   // the only barrier

    // ---- process rows; lane tid owns pixels tid + 256*j ----
    #pragma unroll 1
    for (int r = 0; r < ROWS_PER_BLOCK; ++r) {
        const int y = row0 + r;
        const int rowoff = y * W_IMG;
        const unsigned int* rowbuf = sg2[r];

        // ---- batch ALL 16 DRAM loads for this row back-to-back ----
        float gv[4], Rv[4], Gv[4], Bv[4];
        #pragma unroll
        for (int j = 0; j < 4; ++j) gv[j] = gu[rowoff + tid + (j << 8)];
        #pragma unroll
        for (int j = 0; j < 4; ++j) Rv[j] = im[0 * 1048576 + rowoff + tid + (j << 8)];
        #pragma unroll
        for (int j = 0; j < 4; ++j) Gv[j] = im[1 * 1048576 + rowoff + tid + (j << 8)];
        #pragma unroll
        for (int j = 0; j < 4; ++j) Bv[j] = im[2 * 1048576 + rowoff + tid + (j << 8)];

        #pragma unroll
        for (int j = 0; j < 4; ++j) {
            const int px = tid + (j << 8);

            // z interpolation (guide-driven)
            const float gz  = gv[j] * 8.0f;
            const float fzm = floorf(gz - 0.5f);
            const float tz  = gz - 0.5f - fzm;
            const int   ifz = (int)fzm;
            const int   iz0 = min(max(ifz, 0), GD - 1);
            const int   iz1 = min(max(ifz + 1, 0), GD - 1);
            const float wz0 = 1.0f - tz, wz1 = tz;

            const int o0 = iz0 * ZU + cox0[j];   // (z0,x0)
            const int o1 = iz0 * ZU + cox1[j];   // (z0,x1)
            const int o2 = iz1 * ZU + cox0[j];   // (z1,x0)
            const int o3 = iz1 * ZU + cox1[j];   // (z1,x1)

            // ---- batch ALL tap loads first (8 LDS back-to-back) ----
            const uint4 qa = *reinterpret_cast<const uint4*>(rowbuf + o0);
            const uint4 qb = *reinterpret_cast<const uint4*>(rowbuf + o1);
            const uint4 qc = *reinterpret_cast<const uint4*>(rowbuf + o2);
            const uint4 qd = *reinterpret_cast<const uint4*>(rowbuf + o3);
            const uint2 ra = *reinterpret_cast<const uint2*>(rowbuf + o0 + 4);
            const uint2 rb = *reinterpret_cast<const uint2*>(rowbuf + o1 + 4);
            const uint2 rc = *reinterpret_cast<const uint2*>(rowbuf + o2 + 4);
            const uint2 rd = *reinterpret_cast<const uint2*>(rowbuf + o3 + 4);

            const __half2 wa = __float2half2_rn(wz0 * wxa[j]);
            const __half2 wb = __float2half2_rn(wz0 * wxb[j]);
            const __half2 wc = __float2half2_rn(wz1 * wxa[j]);
            const __half2 wd = __float2half2_rn(wz1 * wxb[j]);

            // ---- 24 HFMA2, no loads interleaved ----
            __half2 a0, a1, a2, a3, a4, a5;
            a0 = __hmul2(u2h(qa.x), wa);
            a1 = __hmul2(u2h(qa.y), wa);
            a2 = __hmul2(u2h(qa.z), wa);
            a3 = __hmul2(u2h(qa.w), wa);
            a4 = __hmul2(u2h(ra.x), wa);
            a5 = __hmul2(u2h(ra.y), wa);

            a0 = __hfma2(u2h(qb.x), wb, a0);
            a1 = __hfma2(u2h(qb.y), wb, a1);
            a2 = __hfma2(u2h(qb.z), wb, a2);
            a3 = __hfma2(u2h(qb.w), wb, a3);
            a4 = __hfma2(u2h(rb.x), wb, a4);
            a5 = __hfma2(u2h(rb.y), wb, a5);

            a0 = __hfma2(u2h(qc.x), wc, a0);
            a1 = __hfma2(u2h(qc.y), wc, a1);
            a2 = __hfma2(u2h(qc.z), wc, a2);
            a3 = __hfma2(u2h(qc.w), wc, a3);
            a4 = __hfma2(u2h(rc.x), wc, a4);
            a5 = __hfma2(u2h(rc.y), wc, a5);

            a0 = __hfma2(u2h(qd.x), wd, a0);
            a1 = __hfma2(u2h(qd.y), wd, a1);
            a2 = __hfma2(u2h(qd.z), wd, a2);
            a3 = __hfma2(u2h(qd.w), wd, a3);
            a4 = __hfma2(u2h(rd.x), wd, a4);
            a5 = __hfma2(u2h(rd.y), wd, a5);

            const float2 p0 = __half22float2(a0);
            const float2 p1 = __half22float2(a1);
            const float2 p2 = __half22float2(a2);
            const float2 p3 = __half22float2(a3);
            const float2 p4 = __half22float2(a4);
            const float2 p5 = __half22float2(a5);

            const float R = Rv[j], G = Gv[j], Bc = Bv[j];
            ob[0 * 1048576 + rowoff + px] =
                fmaf(p0.x, R, fmaf(p0.y, G, fmaf(p1.x, Bc, p1.y)));
            ob[1 * 1048576 + rowoff + px] =
                fmaf(p2.x, R, fmaf(p2.y, G, fmaf(p3.x, Bc, p3.y)));
            ob[2 * 1048576 + rowoff + px] =
                fmaf(p4.x, R, fmaf(p4.y, G, fmaf(p5.x, Bc, p5.y)));
        }
    }
}

extern "C" void kernel_launch(void* const* d_in, const int* in_sizes, int n_in,
                              void* d_out, int out_size)
{
    const float* grid  = nullptr;
    const float* guide = nullptr;
    const float* image = nullptr;
    for (int i = 0; i < n_in; ++i) {
        if (in_sizes[i] == 4 * GRID_PER_B)             grid  = (const float*)d_in[i];
        else if (in_sizes[i] == 4 * H_IMG * W_IMG)     guide = (const float*)d_in[i];
        else if (in_sizes[i] == 4 * 3 * H_IMG * W_IMG) image = (const float*)d_in[i];
    }
    float* out = (float*)d_out;

    dim3 gr(H_IMG / ROWS_PER_BLOCK, 4);   // 256 x 4 = 1024 blocks, 4 rows each
    bsa_kernel<<<gr, 256>>>(grid, guide, image, out);
}